// round 8
// baseline (speedup 1.0000x reference)
#include <cuda_runtime.h>
#include <cuda_fp16.h>
#include <cstdint>
#include <math.h>

#define NA 4096
#define NB 4096
#define D  256
#define H  4
#define DK 64
#define BM 128
#define BN 32
#define KSPLIT 8
#define ITER 16                    // 128 total b-tiles / 8 splits
#define LOG2E 1.4426950408889634f

// ---------------- global scratch (no cudaMalloc allowed) ----------------
__device__ __half g_Q[H * NA * DK];        // pre-scaled by 1/8
__device__ __half g_K[H * NB * DK];
__device__ __half g_Vt[H * DK * NB];       // transposed [head][d][b]
__device__ __half g_ew[(size_t)NA * NB];   // mask ? exp(sani(w)) : 0
__device__ float g_pO[KSPLIT * H * NA * DK];   // partial O
__device__ float g_pl[KSPLIT * H * NA];        // partial row sums
__device__ int   g_mask_is_i32;

typedef unsigned long long u64;
typedef unsigned int u32;

// smem layout (bytes):
//   Q      @0      16384
//   KV[b]  @16384 + b*12288   (K 4096 @+0, Vt 8192 @+4096)
//   E[b]   @40960 + b*10240   (128 rows x 80B pad; 64B data)
#define SMQ    0
#define SMKV(b) (16384 + (b) * 12288)
#define SME(b)  (40960 + (b) * 10240)
#define SM_TOTAL 61440

// ---------------- helpers ----------------
__device__ __forceinline__ u64 pack2(float x, float y) {
    u64 r; asm("mov.b64 %0, {%1,%2};" : "=l"(r) : "f"(x), "f"(y)); return r;
}
__device__ __forceinline__ void unpack2(u64 v, float& x, float& y) {
    asm("mov.b64 {%0,%1}, %2;" : "=f"(x), "=f"(y) : "l"(v));
}
__device__ __forceinline__ u64 fma2(u64 a, u64 b, u64 c) {
    u64 d; asm("fma.rn.f32x2 %0, %1, %2, %3;" : "=l"(d) : "l"(a), "l"(b), "l"(c)); return d;
}
__device__ __forceinline__ float sani(float x) {
    if (isnan(x)) return 0.0f;
    if (isinf(x)) return x > 0.0f ? 1.0f : -1.0f;
    return x;
}
__device__ __forceinline__ float ex2f(float x) {
    float y; asm("ex2.approx.ftz.f32 %0, %1;" : "=f"(y) : "f"(x)); return y;
}
__device__ __forceinline__ u32 smem_u32(const void* p) {
    u32 a; asm("{ .reg .u64 t; cvta.to.shared.u64 t, %1; cvt.u32.u64 %0, t; }" : "=r"(a) : "l"(p));
    return a;
}
__device__ __forceinline__ void cp16(u32 dst, const void* src) {
    asm volatile("cp.async.cg.shared.global [%0], [%1], 16;" :: "r"(dst), "l"(src));
}
__device__ __forceinline__ void cp_commit() { asm volatile("cp.async.commit_group;"); }
__device__ __forceinline__ void cp_wait0()  { asm volatile("cp.async.wait_group 0;"); }

__device__ __forceinline__ void ldsm4(u32 addr, u32& r0, u32& r1, u32& r2, u32& r3) {
    asm volatile("ldmatrix.sync.aligned.m8n8.x4.shared.b16 {%0,%1,%2,%3}, [%4];"
                 : "=r"(r0), "=r"(r1), "=r"(r2), "=r"(r3) : "r"(addr));
}
__device__ __forceinline__ void mma16816(float* c, u32 a0, u32 a1, u32 a2, u32 a3, u32 b0, u32 b1) {
    asm volatile(
        "mma.sync.aligned.m16n8k16.row.col.f32.f16.f16.f32 "
        "{%0,%1,%2,%3}, {%4,%5,%6,%7}, {%8,%9}, {%0,%1,%2,%3};"
        : "+f"(c[0]), "+f"(c[1]), "+f"(c[2]), "+f"(c[3])
        : "r"(a0), "r"(a1), "r"(a2), "r"(a3), "r"(b0), "r"(b1));
}
// pack two floats to f16x2, first arg in low 16 bits
__device__ __forceinline__ u32 packhf(float lo, float hi) {
    u32 d; asm("cvt.rn.f16x2.f32 %0, %1, %2;" : "=r"(d) : "f"(hi), "f"(lo)); return d;
}
__device__ __forceinline__ u32 swaddr(u32 base, int row, int colhalf) {
    int ch = colhalf >> 3;
    return base + row * 128 + (((ch ^ (row & 7)) << 4));
}

// ---------------- mask dtype detector ----------------
__global__ void detect_mask_kernel(const unsigned* __restrict__ m) {
    __shared__ int bad;
    if (threadIdx.x == 0) bad = 0;
    __syncthreads();
    for (int i = threadIdx.x; i < 4096; i += blockDim.x)
        if (m[i] > 1u) bad = 1;
    __syncthreads();
    if (threadIdx.x == 0) g_mask_is_i32 = bad ? 0 : 1;
}

// ---------------- merged projections + E = mask ? exp(sani(w)) : 0 ----------------
#define PSTRIDE 68
__global__ __launch_bounds__(256) void projpack_kernel(
    const float* __restrict__ a_z, const float* __restrict__ bv_z,
    const float* __restrict__ Wq, const float* __restrict__ Wk,
    const float* __restrict__ Wv, const float* __restrict__ weight,
    const unsigned char* __restrict__ m8, const int* __restrict__ m32)
{
    const int z = blockIdx.z;
    const int tid = threadIdx.x;

    if (z == 3) {
        // one thread = 32 cols of one row
        const int w = (blockIdx.x * 32 + blockIdx.y) * 256 + tid;  // 0..524287
        const int row = w >> 7, wc = w & 127;
        const size_t off = (size_t)row * NB + wc * 32;
        const float* wp = weight + off;
        u32 outw[16];
        if (g_mask_is_i32) {
#pragma unroll
            for (int t = 0; t < 8; t++) {
                int4 m = *(const int4*)(m32 + off + t * 4);
                float4 wv = *(const float4*)(wp + t * 4);
                float e0 = m.x ? ex2f(sani(wv.x) * LOG2E) : 0.0f;
                float e1 = m.y ? ex2f(sani(wv.y) * LOG2E) : 0.0f;
                float e2 = m.z ? ex2f(sani(wv.z) * LOG2E) : 0.0f;
                float e3 = m.w ? ex2f(sani(wv.w) * LOG2E) : 0.0f;
                outw[t * 2 + 0] = packhf(e0, e1);
                outw[t * 2 + 1] = packhf(e2, e3);
            }
        } else {
#pragma unroll
            for (int t = 0; t < 8; t++) {
                uchar4 m = *(const uchar4*)(m8 + off + t * 4);
                float4 wv = *(const float4*)(wp + t * 4);
                float e0 = m.x ? ex2f(sani(wv.x) * LOG2E) : 0.0f;
                float e1 = m.y ? ex2f(sani(wv.y) * LOG2E) : 0.0f;
                float e2 = m.z ? ex2f(sani(wv.z) * LOG2E) : 0.0f;
                float e3 = m.w ? ex2f(sani(wv.w) * LOG2E) : 0.0f;
                outw[t * 2 + 0] = packhf(e0, e1);
                outw[t * 2 + 1] = packhf(e2, e3);
            }
        }
        uint4* dst = (uint4*)(g_ew + off);
#pragma unroll
        for (int t = 0; t < 4; t++)
            dst[t] = make_uint4(outw[4 * t], outw[4 * t + 1], outw[4 * t + 2], outw[4 * t + 3]);
        return;
    }

    if (blockIdx.y >= 4) return;

    __shared__ float Xs[32][PSTRIDE];
    __shared__ float Ws[32][PSTRIDE];

    const float* X = (z == 0) ? a_z : bv_z;
    const float* W = (z == 0) ? Wq : (z == 1) ? Wk : Wv;
    const float outscale = (z == 0) ? 0.125f : 1.0f;

    const int tx = tid & 15, ty = tid >> 4;
    const int r0 = blockIdx.x * 64, c0 = blockIdx.y * 64;

    u64 acc[2][4];
#pragma unroll
    for (int p = 0; p < 2; p++)
#pragma unroll
        for (int j = 0; j < 4; j++) acc[p][j] = 0ull;

    for (int k0 = 0; k0 < D; k0 += 32) {
        __syncthreads();
#pragma unroll
        for (int s = 0; s < 2; s++) {
            int idx = tid * 2 + s;
            int row = idx >> 3;
            int k4  = (idx & 7) * 4;
            float4 v = *(const float4*)&X[(size_t)(r0 + row) * D + k0 + k4];
            Xs[k4 + 0][row] = sani(v.x);
            Xs[k4 + 1][row] = sani(v.y);
            Xs[k4 + 2][row] = sani(v.z);
            Xs[k4 + 3][row] = sani(v.w);
            float4 w = *(const float4*)&W[(size_t)(c0 + row) * D + k0 + k4];
            Ws[k4 + 0][row] = w.x;
            Ws[k4 + 1][row] = w.y;
            Ws[k4 + 2][row] = w.z;
            Ws[k4 + 3][row] = w.w;
        }
        __syncthreads();
#pragma unroll 8
        for (int kk = 0; kk < 32; kk++) {
            const u64* ap = (const u64*)&Xs[kk][ty * 4];
            u64 a0 = ap[0], a1 = ap[1];
            float4 b = *(const float4*)&Ws[kk][tx * 4];
            u64 b0 = pack2(b.x, b.x), b1 = pack2(b.y, b.y);
            u64 b2 = pack2(b.z, b.z), b3 = pack2(b.w, b.w);
            acc[0][0] = fma2(a0, b0, acc[0][0]);
            acc[0][1] = fma2(a0, b1, acc[0][1]);
            acc[0][2] = fma2(a0, b2, acc[0][2]);
            acc[0][3] = fma2(a0, b3, acc[0][3]);
            acc[1][0] = fma2(a1, b0, acc[1][0]);
            acc[1][1] = fma2(a1, b1, acc[1][1]);
            acc[1][2] = fma2(a1, b2, acc[1][2]);
            acc[1][3] = fma2(a1, b3, acc[1][3]);
        }
    }
#pragma unroll
    for (int p = 0; p < 2; p++)
#pragma unroll
        for (int j = 0; j < 4; j++) {
            float x, y; unpack2(acc[p][j], x, y);
            x *= outscale; y *= outscale;
            const int rr = r0 + ty * 4 + p * 2;
            const int c  = c0 + tx * 4 + j;
            const int hd = c >> 6, hc = c & 63;
            __half xh = __float2half(x);
            __half yh = __float2half(y);
            if (z == 0) {
                size_t o = ((size_t)hd * NA + rr) * DK + hc;
                g_Q[o] = xh;
                g_Q[o + DK] = yh;
            } else if (z == 1) {
                size_t o = ((size_t)hd * NB + rr) * DK + hc;
                g_K[o] = xh;
                g_K[o + DK] = yh;
            } else {
                size_t o = ((size_t)hd * DK + hc) * NB + rr;
                g_Vt[o] = xh;
                g_Vt[o + 1] = yh;
            }
        }
}

// ---------------- async tile loads ----------------
__device__ __forceinline__ void load_kve_async(u32 sb, int buf, int head, int b0,
                                               int q0, int tid) {
    const u32 base = sb + SMKV(buf);
#pragma unroll
    for (int s = 0; s < 2; s++) {   // K: 32 rows x 8 chunks (swizzled)
        int idx = tid + s * 128;
        int row = idx >> 3, ch = idx & 7;
        const __half* src = g_K + ((size_t)head * NB + b0 + row) * DK + ch * 8;
        cp16(base + row * 128 + ((ch ^ (row & 7)) << 4), src);
    }
#pragma unroll
    for (int s = 0; s < 2; s++) {   // Vt: 64 rows x 4 chunks (swizzled)
        int idx = tid + s * 128;
        int row = idx >> 2, ch = idx & 3;
        const __half* src = g_Vt + ((size_t)head * DK + row) * NB + b0 + ch * 8;
        cp16(base + 4096 + row * 128 + ((ch ^ (row & 7)) << 4), src);
    }
    const u32 ebase = sb + SME(buf);
#pragma unroll
    for (int s = 0; s < 4; s++) {   // E: 128 rows x 4 chunks, 80B row pitch (no swizzle)
        int idx = tid + s * 128;
        int row = idx >> 2, ch = idx & 3;
        const __half* src = g_ew + (size_t)(q0 + row) * NB + b0 + ch * 8;
        cp16(ebase + row * 80 + ch * 16, src);
    }
}

// ---------------- fused flash attention: folded-E softmax, 8-way split-KV ----------------
__global__ __launch_bounds__(128, 3) void attn_kernel()
{
    extern __shared__ char smch[];
    const u32 sb = smem_u32(smch);
    const int tid = threadIdx.x;
    const int w = tid >> 5, lane = tid & 31;
    const int g = lane >> 2, qd = lane & 3;
    const int head = blockIdx.x;
    const int q0 = blockIdx.y * BM;
    const int split = blockIdx.z;
    const int istart = split * ITER;

    const int aRow = (lane & 7) + ((lane >> 3) & 1) * 8;
    const int aCol = ((lane >> 4) & 1) * 8;
    const int bRow = (lane & 7) + ((lane >> 4) & 1) * 8;
    const int bCol = ((lane >> 3) & 1) * 8;

    // ---- prologue: Q + KVE buf0 ----
#pragma unroll
    for (int s = 0; s < 8; s++) {
        int idx = tid + s * 128;
        int row = idx >> 3;
        int ch  = idx & 7;
        const __half* src = g_Q + ((size_t)head * NA + q0 + row) * DK + ch * 8;
        cp16(sb + SMQ + row * 128 + ((ch ^ (row & 7)) << 4), src);
    }
    load_kve_async(sb, 0, head, istart * BN, q0, tid);
    cp_commit();
    cp_wait0();
    __syncthreads();

    // ---- Q fragments: 2 row-tiles x 4 k-tiles ----
    const int r0 = w * 32;
    u32 qh[2][4][4];
#pragma unroll
    for (int rt = 0; rt < 2; rt++)
#pragma unroll
        for (int kt = 0; kt < 4; kt++)
            ldsm4(swaddr(sb + SMQ, r0 + rt * 16 + aRow, kt * 16 + aCol),
                  qh[rt][kt][0], qh[rt][kt][1], qh[rt][kt][2], qh[rt][kt][3]);

    float oacc[2][8][4];
#pragma unroll
    for (int rt = 0; rt < 2; rt++)
#pragma unroll
        for (int j = 0; j < 8; j++)
#pragma unroll
            for (int e = 0; e < 4; e++) oacc[rt][j][e] = 0.0f;
    float lsum[2][2] = {{0.f, 0.f}, {0.f, 0.f}};

    const int rbase = q0 + r0 + g;
    const int wrow0 = r0 + g;
    const __half2 CHI2 = __float2half2_rn(22026.465f);    // e^10
    const __half2 CLO2 = __float2half2_rn(4.5399930e-5f); // e^-10

    for (int i = 0; i < ITER; i++) {
        const int cur = i & 1;

        if (i + 1 < ITER) {
            load_kve_async(sb, cur ^ 1, head, (istart + i + 1) * BN, q0, tid);
            cp_commit();
        }

        // ---- S = (Q/8) K^T : shared K frags across both row-tiles ----
        float sacc[2][4][4];
#pragma unroll
        for (int rt = 0; rt < 2; rt++)
#pragma unroll
            for (int j = 0; j < 4; j++)
#pragma unroll
                for (int e = 0; e < 4; e++) sacc[rt][j][e] = 0.0f;

        const u32 kB = sb + SMKV(cur);
#pragma unroll
        for (int kt = 0; kt < 4; kt++) {
#pragma unroll
            for (int jp = 0; jp < 2; jp++) {
                u32 k0r, k1r, k2r, k3r;
                ldsm4(swaddr(kB, jp * 16 + bRow, kt * 16 + bCol), k0r, k1r, k2r, k3r);
#pragma unroll
                for (int rt = 0; rt < 2; rt++) {
                    mma16816(sacc[rt][2 * jp],     qh[rt][kt][0], qh[rt][kt][1], qh[rt][kt][2], qh[rt][kt][3], k0r, k1r);
                    mma16816(sacc[rt][2 * jp + 1], qh[rt][kt][0], qh[rt][kt][1], qh[rt][kt][2], qh[rt][kt][3], k2r, k3r);
                }
            }
        }

        // ---- softmax: P = clamp(exp(s)*E, e^-10, e^10); masked E=0 -> P=e^-10 ----
        const int eoff = SME(cur);
        u32 phf[2][4][2];
#pragma unroll
        for (int rt = 0; rt < 2; rt++) {
            const int rA = wrow0 + rt * 16;
            const int rB = rA + 8;
#pragma unroll
            for (int j = 0; j < 4; j++) {
                u32 eA = *(const u32*)(smch + eoff + rA * 80 + j * 16 + qd * 4);
                u32 eBv = *(const u32*)(smch + eoff + rB * 80 + j * 16 + qd * 4);
                float p0 = ex2f(sacc[rt][j][0] * LOG2E);
                float p1 = ex2f(sacc[rt][j][1] * LOG2E);
                float p2 = ex2f(sacc[rt][j][2] * LOG2E);
                float p3 = ex2f(sacc[rt][j][3] * LOG2E);
                u32 psA = packhf(p0, p1);
                u32 psB = packhf(p2, p3);
                __half2 PA = __hmul2(*(const __half2*)&psA, *(const __half2*)&eA);
                __half2 PB = __hmul2(*(const __half2*)&psB, *(const __half2*)&eBv);
                PA = __hmax2(__hmin2(PA, CHI2), CLO2);
                PB = __hmax2(__hmin2(PB, CHI2), CLO2);
                float2 fA = __half22float2(PA);
                float2 fB = __half22float2(PB);
                lsum[rt][0] += fA.x + fA.y;
                lsum[rt][1] += fB.x + fB.y;
                phf[rt][j][0] = *(const u32*)&PA;
                phf[rt][j][1] = *(const u32*)&PB;
            }
        }

        // ---- O += P @ V : shared V frags across both row-tiles ----
        const u32 vB = sb + SMKV(cur) + 4096;
#pragma unroll
        for (int kt = 0; kt < 2; kt++) {
#pragma unroll
            for (int jp = 0; jp < 4; jp++) {
                u32 v0r, v1r, v2r, v3r;
                ldsm4(swaddr(vB, jp * 16 + bRow, kt * 16 + bCol), v0r, v1r, v2r, v3r);
#pragma unroll
                for (int rt = 0; rt < 2; rt++) {
                    u32 a0 = phf[rt][2 * kt][0], a1 = phf[rt][2 * kt][1];
                    u32 a2 = phf[rt][2 * kt + 1][0], a3 = phf[rt][2 * kt + 1][1];
                    mma16816(oacc[rt][2 * jp],     a0, a1, a2, a3, v0r, v1r);
                    mma16816(oacc[rt][2 * jp + 1], a0, a1, a2, a3, v2r, v3r);
                }
            }
        }

        if (i + 1 < ITER) cp_wait0();
        __syncthreads();
    }

    // ---- epilogue: partial O + partial l (additive across splits) ----
    const size_t po = ((size_t)(split * H + head) * NA);
#pragma unroll
    for (int rt = 0; rt < 2; rt++) {
        float lA = lsum[rt][0], lB = lsum[rt][1];
        lA += __shfl_xor_sync(0xffffffffu, lA, 1);
        lA += __shfl_xor_sync(0xffffffffu, lA, 2);
        lB += __shfl_xor_sync(0xffffffffu, lB, 1);
        lB += __shfl_xor_sync(0xffffffffu, lB, 2);
        const int rGA = rbase + rt * 16;
        const int rGB = rGA + 8;
        if (qd == 0) {
            g_pl[po + rGA] = lA;
            g_pl[po + rGB] = lB;
        }
        float* pA = g_pO + (po + rGA) * DK + qd * 2;
        float* pB = g_pO + (po + rGB) * DK + qd * 2;
#pragma unroll
        for (int j = 0; j < 8; j++) {
            *(float2*)(pA + j * 8) = make_float2(oacc[rt][j][0], oacc[rt][j][1]);
            *(float2*)(pB + j * 8) = make_float2(oacc[rt][j][2], oacc[rt][j][3]);
        }
    }
}

// ---------------- finalize: combine splits, head mean, influence ----------------
__global__ __launch_bounds__(256) void finalize_kernel(float* __restrict__ out)
{
    int idx = blockIdx.x * blockDim.x + threadIdx.x;   // 0..65535
    if (idx < NA * DK / 4) {
        const int row = idx >> 4;
        const int c4 = (idx & 15) * 4;
        float ax = 0.f, ay = 0.f, az = 0.f, aw = 0.f;
#pragma unroll
        for (int h = 0; h < H; h++) {
            float ox = 0.f, oy = 0.f, oz = 0.f, ow = 0.f, l = 0.f;
#pragma unroll
            for (int s = 0; s < KSPLIT; s++) {
                const float4 v = *(const float4*)&g_pO[((size_t)(s * H + h) * NA + row) * DK + c4];
                ox += v.x; oy += v.y; oz += v.z; ow += v.w;
                l += g_pl[(size_t)(s * H + h) * NA + row];
            }
            const float inv = 1.0f / l;
            ax += ox * inv; ay += oy * inv; az += oz * inv; aw += ow * inv;
        }
        *(float4*)&out[(size_t)row * DK + c4] =
            make_float4(ax * 0.25f, ay * 0.25f, az * 0.25f, aw * 0.25f);
    }
    if (idx < NA) {
        out[NA * DK + idx] = 1.0f;   // softmax rows sum to exactly 1
    }
}

// ---------------- launch ----------------
extern "C" void kernel_launch(void* const* d_in, const int* in_sizes, int n_in,
                              void* d_out, int out_size)
{
    const float* a_z    = (const float*)d_in[0];
    const float* bv_z   = (const float*)d_in[1];
    const void*  maskp  = d_in[2];
    const float* weight = (const float*)d_in[3];
    const float* Wq     = (const float*)d_in[4];
    const float* Wk     = (const float*)d_in[5];
    const float* Wv     = (const float*)d_in[6];
    float* out = (float*)d_out;

    cudaFuncSetAttribute(attn_kernel, cudaFuncAttributeMaxDynamicSharedMemorySize, SM_TOTAL);

    detect_mask_kernel<<<1, 256>>>((const unsigned*)maskp);
    projpack_kernel<<<dim3(64, 32, 4), 256>>>(a_z, bv_z, Wq, Wk, Wv, weight,
        (const unsigned char*)maskp, (const int*)maskp);
    attn_kernel<<<dim3(H, NA / BM, KSPLIT), 128, SM_TOTAL>>>();
    finalize_kernel<<<(NA * DK / 4 + 255) / 256, 256>>>(out);
}

// round 10
// speedup vs baseline: 1.5163x; 1.5163x over previous
#include <cuda_runtime.h>
#include <cuda_fp16.h>
#include <cstdint>
#include <math.h>

#define NA 4096
#define NB 4096
#define D  256
#define H  4
#define DK 64
#define BM 128
#define BN 32
#define KSPLIT 2
#define KVLEN (NB / KSPLIT)        // 2048
#define NITER (KVLEN / BN)         // 64
#define LOG2E 1.4426950408889634f

// ---------------- global scratch (no cudaMalloc allowed) ----------------
__device__ __half g_Q[H * NA * DK];        // pre-scaled by 1/8
__device__ __half g_K[H * NB * DK];
__device__ __half g_Vt[H * DK * NB];       // transposed [head][d][b]
__device__ __half g_ew[(size_t)NA * NB];   // mask ? exp(sani(w)) : 0
__device__ float g_pO[KSPLIT * H * NA * DK];   // partial O
__device__ float g_pl[KSPLIT * H * NA];        // partial row sums
__device__ int   g_mask_is_i32;

typedef unsigned long long u64;
typedef unsigned int u32;

// smem layout (bytes):
//   Q      @0      16384
//   KV[b]  @16384 + b*12288   (K 4096 @+0, Vt 8192 @+4096)
//   E[b]   @40960 + b*10240   (128 rows x 80B pitch; 64B data)
#define SMQ    0
#define SMKV(b) (16384 + (b) * 12288)
#define SME(b)  (40960 + (b) * 10240)
#define SM_TOTAL 61440

// ---------------- helpers ----------------
__device__ __forceinline__ u64 pack2(float x, float y) {
    u64 r; asm("mov.b64 %0, {%1,%2};" : "=l"(r) : "f"(x), "f"(y)); return r;
}
__device__ __forceinline__ void unpack2(u64 v, float& x, float& y) {
    asm("mov.b64 {%0,%1}, %2;" : "=f"(x), "=f"(y) : "l"(v));
}
__device__ __forceinline__ u64 fma2(u64 a, u64 b, u64 c) {
    u64 d; asm("fma.rn.f32x2 %0, %1, %2, %3;" : "=l"(d) : "l"(a), "l"(b), "l"(c)); return d;
}
__device__ __forceinline__ float sani(float x) {
    if (isnan(x)) return 0.0f;
    if (isinf(x)) return x > 0.0f ? 1.0f : -1.0f;
    return x;
}
__device__ __forceinline__ float ex2f(float x) {
    float y; asm("ex2.approx.ftz.f32 %0, %1;" : "=f"(y) : "f"(x)); return y;
}
__device__ __forceinline__ u32 smem_u32(const void* p) {
    u32 a; asm("{ .reg .u64 t; cvta.to.shared.u64 t, %1; cvt.u32.u64 %0, t; }" : "=r"(a) : "l"(p));
    return a;
}
__device__ __forceinline__ void cp16(u32 dst, const void* src) {
    asm volatile("cp.async.cg.shared.global [%0], [%1], 16;" :: "r"(dst), "l"(src));
}
__device__ __forceinline__ void cp_commit() { asm volatile("cp.async.commit_group;"); }
__device__ __forceinline__ void cp_wait0()  { asm volatile("cp.async.wait_group 0;"); }

__device__ __forceinline__ void ldsm4(u32 addr, u32& r0, u32& r1, u32& r2, u32& r3) {
    asm volatile("ldmatrix.sync.aligned.m8n8.x4.shared.b16 {%0,%1,%2,%3}, [%4];"
                 : "=r"(r0), "=r"(r1), "=r"(r2), "=r"(r3) : "r"(addr));
}
__device__ __forceinline__ void mma16816(float* c, u32 a0, u32 a1, u32 a2, u32 a3, u32 b0, u32 b1) {
    asm volatile(
        "mma.sync.aligned.m16n8k16.row.col.f32.f16.f16.f32 "
        "{%0,%1,%2,%3}, {%4,%5,%6,%7}, {%8,%9}, {%0,%1,%2,%3};"
        : "+f"(c[0]), "+f"(c[1]), "+f"(c[2]), "+f"(c[3])
        : "r"(a0), "r"(a1), "r"(a2), "r"(a3), "r"(b0), "r"(b1));
}
// pack two floats to f16x2, first arg in low 16 bits
__device__ __forceinline__ u32 packhf(float lo, float hi) {
    u32 d; asm("cvt.rn.f16x2.f32 %0, %1, %2;" : "=r"(d) : "f"(hi), "f"(lo)); return d;
}
__device__ __forceinline__ u32 swaddr(u32 base, int row, int colhalf) {
    int ch = colhalf >> 3;
    return base + row * 128 + (((ch ^ (row & 7)) << 4));
}

// ---------------- mask dtype detector ----------------
__global__ void detect_mask_kernel(const unsigned* __restrict__ m) {
    __shared__ int bad;
    if (threadIdx.x == 0) bad = 0;
    __syncthreads();
    for (int i = threadIdx.x; i < 4096; i += blockDim.x)
        if (m[i] > 1u) bad = 1;
    __syncthreads();
    if (threadIdx.x == 0) g_mask_is_i32 = bad ? 0 : 1;
}

// ---------------- merged projections + E = mask ? exp(sani(w)) : 0 ----------------
#define PSTRIDE 68
__global__ __launch_bounds__(256) void projpack_kernel(
    const float* __restrict__ a_z, const float* __restrict__ bv_z,
    const float* __restrict__ Wq, const float* __restrict__ Wk,
    const float* __restrict__ Wv, const float* __restrict__ weight,
    const unsigned char* __restrict__ m8, const int* __restrict__ m32)
{
    const int z = blockIdx.z;
    const int tid = threadIdx.x;

    if (z == 3) {
        // one thread = 32 cols of one row
        const int w = (blockIdx.x * 32 + blockIdx.y) * 256 + tid;  // 0..524287
        const int row = w >> 7, wc = w & 127;
        const size_t off = (size_t)row * NB + wc * 32;
        const float* wp = weight + off;
        u32 outw[16];
        if (g_mask_is_i32) {
#pragma unroll
            for (int t = 0; t < 8; t++) {
                int4 m = *(const int4*)(m32 + off + t * 4);
                float4 wv = *(const float4*)(wp + t * 4);
                float e0 = m.x ? ex2f(sani(wv.x) * LOG2E) : 0.0f;
                float e1 = m.y ? ex2f(sani(wv.y) * LOG2E) : 0.0f;
                float e2 = m.z ? ex2f(sani(wv.z) * LOG2E) : 0.0f;
                float e3 = m.w ? ex2f(sani(wv.w) * LOG2E) : 0.0f;
                outw[t * 2 + 0] = packhf(e0, e1);
                outw[t * 2 + 1] = packhf(e2, e3);
            }
        } else {
#pragma unroll
            for (int t = 0; t < 8; t++) {
                uchar4 m = *(const uchar4*)(m8 + off + t * 4);
                float4 wv = *(const float4*)(wp + t * 4);
                float e0 = m.x ? ex2f(sani(wv.x) * LOG2E) : 0.0f;
                float e1 = m.y ? ex2f(sani(wv.y) * LOG2E) : 0.0f;
                float e2 = m.z ? ex2f(sani(wv.z) * LOG2E) : 0.0f;
                float e3 = m.w ? ex2f(sani(wv.w) * LOG2E) : 0.0f;
                outw[t * 2 + 0] = packhf(e0, e1);
                outw[t * 2 + 1] = packhf(e2, e3);
            }
        }
        uint4* dst = (uint4*)(g_ew + off);
#pragma unroll
        for (int t = 0; t < 4; t++)
            dst[t] = make_uint4(outw[4 * t], outw[4 * t + 1], outw[4 * t + 2], outw[4 * t + 3]);
        return;
    }

    if (blockIdx.y >= 4) return;

    __shared__ float Xs[32][PSTRIDE];
    __shared__ float Ws[32][PSTRIDE];

    const float* X = (z == 0) ? a_z : bv_z;
    const float* W = (z == 0) ? Wq : (z == 1) ? Wk : Wv;
    const float outscale = (z == 0) ? 0.125f : 1.0f;

    const int tx = tid & 15, ty = tid >> 4;
    const int r0 = blockIdx.x * 64, c0 = blockIdx.y * 64;

    u64 acc[2][4];
#pragma unroll
    for (int p = 0; p < 2; p++)
#pragma unroll
        for (int j = 0; j < 4; j++) acc[p][j] = 0ull;

    for (int k0 = 0; k0 < D; k0 += 32) {
        __syncthreads();
#pragma unroll
        for (int s = 0; s < 2; s++) {
            int idx = tid * 2 + s;
            int row = idx >> 3;
            int k4  = (idx & 7) * 4;
            float4 v = *(const float4*)&X[(size_t)(r0 + row) * D + k0 + k4];
            Xs[k4 + 0][row] = sani(v.x);
            Xs[k4 + 1][row] = sani(v.y);
            Xs[k4 + 2][row] = sani(v.z);
            Xs[k4 + 3][row] = sani(v.w);
            float4 w = *(const float4*)&W[(size_t)(c0 + row) * D + k0 + k4];
            Ws[k4 + 0][row] = w.x;
            Ws[k4 + 1][row] = w.y;
            Ws[k4 + 2][row] = w.z;
            Ws[k4 + 3][row] = w.w;
        }
        __syncthreads();
#pragma unroll 8
        for (int kk = 0; kk < 32; kk++) {
            const u64* ap = (const u64*)&Xs[kk][ty * 4];
            u64 a0 = ap[0], a1 = ap[1];
            float4 b = *(const float4*)&Ws[kk][tx * 4];
            u64 b0 = pack2(b.x, b.x), b1 = pack2(b.y, b.y);
            u64 b2 = pack2(b.z, b.z), b3 = pack2(b.w, b.w);
            acc[0][0] = fma2(a0, b0, acc[0][0]);
            acc[0][1] = fma2(a0, b1, acc[0][1]);
            acc[0][2] = fma2(a0, b2, acc[0][2]);
            acc[0][3] = fma2(a0, b3, acc[0][3]);
            acc[1][0] = fma2(a1, b0, acc[1][0]);
            acc[1][1] = fma2(a1, b1, acc[1][1]);
            acc[1][2] = fma2(a1, b2, acc[1][2]);
            acc[1][3] = fma2(a1, b3, acc[1][3]);
        }
    }
#pragma unroll
    for (int p = 0; p < 2; p++)
#pragma unroll
        for (int j = 0; j < 4; j++) {
            float x, y; unpack2(acc[p][j], x, y);
            x *= outscale; y *= outscale;
            const int rr = r0 + ty * 4 + p * 2;
            const int c  = c0 + tx * 4 + j;
            const int hd = c >> 6, hc = c & 63;
            __half xh = __float2half(x);
            __half yh = __float2half(y);
            if (z == 0) {
                size_t o = ((size_t)hd * NA + rr) * DK + hc;
                g_Q[o] = xh;
                g_Q[o + DK] = yh;
            } else if (z == 1) {
                size_t o = ((size_t)hd * NB + rr) * DK + hc;
                g_K[o] = xh;
                g_K[o + DK] = yh;
            } else {
                size_t o = ((size_t)hd * DK + hc) * NB + rr;
                g_Vt[o] = xh;
                g_Vt[o + 1] = yh;
            }
        }
}

// ---------------- async tile loads (256 threads: 4 chunks each) ----------------
__device__ __forceinline__ void load_kve_async(u32 sb, int buf, int head, int b0,
                                               int q0, int tid) {
    const u32 base = sb + SMKV(buf);
    {   // K: 32 rows x 8 chunks (swizzled)
        int row = tid >> 3, ch = tid & 7;
        const __half* src = g_K + ((size_t)head * NB + b0 + row) * DK + ch * 8;
        cp16(base + row * 128 + ((ch ^ (row & 7)) << 4), src);
    }
    {   // Vt: 64 rows x 4 chunks (swizzled)
        int row = tid >> 2, ch = tid & 3;
        const __half* src = g_Vt + ((size_t)head * DK + row) * NB + b0 + ch * 8;
        cp16(base + 4096 + row * 128 + ((ch ^ (row & 7)) << 4), src);
    }
    const u32 ebase = sb + SME(buf);
#pragma unroll
    for (int s = 0; s < 2; s++) {   // E: 128 rows x 4 chunks, 80B pitch (no swizzle)
        int idx = tid + s * 256;
        int row = idx >> 2, ch = idx & 3;
        const __half* src = g_ew + (size_t)(q0 + row) * NB + b0 + ch * 8;
        cp16(ebase + row * 80 + ch * 16, src);
    }
}

// ---------------- fused flash attention: 8 warps M=16, folded-E softmax ----------------
__global__ __launch_bounds__(256, 2) void attn_kernel()
{
    extern __shared__ char smch[];
    const u32 sb = smem_u32(smch);
    const int tid = threadIdx.x;
    const int wid = tid >> 5, lane = tid & 31;
    const int g = lane >> 2, qd = lane & 3;
    const int head = blockIdx.x;
    const int q0 = blockIdx.y * BM;
    const int split = blockIdx.z;
    const int bbase = split * KVLEN;

    const int aRow = (lane & 7) + ((lane >> 3) & 1) * 8;
    const int aCol = ((lane >> 4) & 1) * 8;
    const int bRow = (lane & 7) + ((lane >> 4) & 1) * 8;
    const int bCol = ((lane >> 3) & 1) * 8;

    // ---- prologue: Q + KVE buf0 ----
#pragma unroll
    for (int s = 0; s < 4; s++) {
        int idx = tid + s * 256;
        int row = idx >> 3;
        int ch  = idx & 7;
        const __half* src = g_Q + ((size_t)head * NA + q0 + row) * DK + ch * 8;
        cp16(sb + SMQ + row * 128 + ((ch ^ (row & 7)) << 4), src);
    }
    load_kve_async(sb, 0, head, bbase, q0, tid);
    cp_commit();
    cp_wait0();
    __syncthreads();

    // ---- Q fragments (persistent) ----
    const int r0 = wid * 16;
    u32 qh[4][4];
#pragma unroll
    for (int kt = 0; kt < 4; kt++)
        ldsm4(swaddr(sb + SMQ, r0 + aRow, kt * 16 + aCol),
              qh[kt][0], qh[kt][1], qh[kt][2], qh[kt][3]);

    float oacc[8][4];
#pragma unroll
    for (int j = 0; j < 8; j++)
#pragma unroll
        for (int e = 0; e < 4; e++) oacc[j][e] = 0.0f;
    float lsumA = 0.0f, lsumB = 0.0f;

    const int rA = r0 + g;            // local q row (low); +8 = high
    const int rbase = q0 + rA;
    const __half2 CHI2 = __float2half2_rn(22026.465f);    // e^10
    const __half2 CLO2 = __float2half2_rn(4.5399930e-5f); // e^-10

    for (int i = 0; i < NITER; i++) {
        const int cur = i & 1;
        const int b0 = bbase + i * BN;

        if (i + 1 < NITER) {
            load_kve_async(sb, cur ^ 1, head, b0 + BN, q0, tid);
            cp_commit();
        }

        // ---- S = (Q/8) K^T ----
        float sacc[4][4];
#pragma unroll
        for (int j = 0; j < 4; j++)
#pragma unroll
            for (int e = 0; e < 4; e++) sacc[j][e] = 0.0f;

        const u32 kB = sb + SMKV(cur);
#pragma unroll
        for (int kt = 0; kt < 4; kt++) {
#pragma unroll
            for (int jp = 0; jp < 2; jp++) {
                u32 k0r, k1r, k2r, k3r;
                ldsm4(swaddr(kB, jp * 16 + bRow, kt * 16 + bCol), k0r, k1r, k2r, k3r);
                mma16816(sacc[2 * jp],     qh[kt][0], qh[kt][1], qh[kt][2], qh[kt][3], k0r, k1r);
                mma16816(sacc[2 * jp + 1], qh[kt][0], qh[kt][1], qh[kt][2], qh[kt][3], k2r, k3r);
            }
        }

        // ---- softmax: P = clamp(exp(s)*E, e^-10, e^10); masked E=0 -> P=e^-10 ----
        const int eoff = SME(cur);
        u32 phf[4][2];
#pragma unroll
        for (int j = 0; j < 4; j++) {
            u32 eA  = *(const u32*)(smch + eoff + rA * 80 + j * 16 + qd * 4);
            u32 eBv = *(const u32*)(smch + eoff + (rA + 8) * 80 + j * 16 + qd * 4);
            float p0 = ex2f(sacc[j][0] * LOG2E);
            float p1 = ex2f(sacc[j][1] * LOG2E);
            float p2 = ex2f(sacc[j][2] * LOG2E);
            float p3 = ex2f(sacc[j][3] * LOG2E);
            u32 psA = packhf(p0, p1);
            u32 psB = packhf(p2, p3);
            __half2 PA = __hmul2(*(const __half2*)&psA, *(const __half2*)&eA);
            __half2 PB = __hmul2(*(const __half2*)&psB, *(const __half2*)&eBv);
            PA = __hmax2(__hmin2(PA, CHI2), CLO2);
            PB = __hmax2(__hmin2(PB, CHI2), CLO2);
            float2 fA = __half22float2(PA);
            float2 fB = __half22float2(PB);
            lsumA += fA.x + fA.y;
            lsumB += fB.x + fB.y;
            phf[j][0] = *(const u32*)&PA;
            phf[j][1] = *(const u32*)&PB;
        }

        // ---- O += P @ V ----
        const u32 vB = sb + SMKV(cur) + 4096;
#pragma unroll
        for (int kt = 0; kt < 2; kt++) {
            u32 a0 = phf[2 * kt][0], a1 = phf[2 * kt][1];
            u32 a2 = phf[2 * kt + 1][0], a3 = phf[2 * kt + 1][1];
#pragma unroll
            for (int jp = 0; jp < 4; jp++) {
                u32 v0r, v1r, v2r, v3r;
                ldsm4(swaddr(vB, jp * 16 + bRow, kt * 16 + bCol), v0r, v1r, v2r, v3r);
                mma16816(oacc[2 * jp],     a0, a1, a2, a3, v0r, v1r);
                mma16816(oacc[2 * jp + 1], a0, a1, a2, a3, v2r, v3r);
            }
        }

        if (i + 1 < NITER) cp_wait0();
        __syncthreads();
    }

    // ---- epilogue: partial O + partial l (additive across splits) ----
    lsumA += __shfl_xor_sync(0xffffffffu, lsumA, 1);
    lsumA += __shfl_xor_sync(0xffffffffu, lsumA, 2);
    lsumB += __shfl_xor_sync(0xffffffffu, lsumB, 1);
    lsumB += __shfl_xor_sync(0xffffffffu, lsumB, 2);

    const size_t po = ((size_t)(split * H + head) * NA);
    const int rGA = rbase, rGB = rbase + 8;
    if (qd == 0) {
        g_pl[po + rGA] = lsumA;
        g_pl[po + rGB] = lsumB;
    }
    float* pA = g_pO + (po + rGA) * DK + qd * 2;
    float* pB = g_pO + (po + rGB) * DK + qd * 2;
#pragma unroll
    for (int j = 0; j < 8; j++) {
        *(float2*)(pA + j * 8) = make_float2(oacc[j][0], oacc[j][1]);
        *(float2*)(pB + j * 8) = make_float2(oacc[j][2], oacc[j][3]);
    }
}

// ---------------- finalize: combine splits, head mean, influence ----------------
__global__ __launch_bounds__(256) void finalize_kernel(float* __restrict__ out)
{
    int idx = blockIdx.x * blockDim.x + threadIdx.x;   // 0..65535
    if (idx < NA * DK / 4) {
        const int row = idx >> 4;
        const int c4 = (idx & 15) * 4;
        float ax = 0.f, ay = 0.f, az = 0.f, aw = 0.f;
#pragma unroll
        for (int h = 0; h < H; h++) {
            float ox = 0.f, oy = 0.f, oz = 0.f, ow = 0.f, l = 0.f;
#pragma unroll
            for (int s = 0; s < KSPLIT; s++) {
                const float4 v = *(const float4*)&g_pO[((size_t)(s * H + h) * NA + row) * DK + c4];
                ox += v.x; oy += v.y; oz += v.z; ow += v.w;
                l += g_pl[(size_t)(s * H + h) * NA + row];
            }
            const float inv = 1.0f / l;
            ax += ox * inv; ay += oy * inv; az += oz * inv; aw += ow * inv;
        }
        *(float4*)&out[(size_t)row * DK + c4] =
            make_float4(ax * 0.25f, ay * 0.25f, az * 0.25f, aw * 0.25f);
    }
    if (idx < NA) {
        out[NA * DK + idx] = 1.0f;   // softmax rows sum to exactly 1
    }
}

// ---------------- launch ----------------
extern "C" void kernel_launch(void* const* d_in, const int* in_sizes, int n_in,
                              void* d_out, int out_size)
{
    const float* a_z    = (const float*)d_in[0];
    const float* bv_z   = (const float*)d_in[1];
    const void*  maskp  = d_in[2];
    const float* weight = (const float*)d_in[3];
    const float* Wq     = (const float*)d_in[4];
    const float* Wk     = (const float*)d_in[5];
    const float* Wv     = (const float*)d_in[6];
    float* out = (float*)d_out;

    cudaFuncSetAttribute(attn_kernel, cudaFuncAttributeMaxDynamicSharedMemorySize, SM_TOTAL);

    detect_mask_kernel<<<1, 256>>>((const unsigned*)maskp);
    projpack_kernel<<<dim3(64, 32, 4), 256>>>(a_z, bv_z, Wq, Wk, Wv, weight,
        (const unsigned char*)maskp, (const int*)maskp);
    attn_kernel<<<dim3(H, NA / BM, KSPLIT), 256, SM_TOTAL>>>();
    finalize_kernel<<<(NA * DK / 4 + 255) / 256, 256>>>(out);
}

// round 11
// speedup vs baseline: 1.5530x; 1.0242x over previous
#include <cuda_runtime.h>
#include <cuda_fp16.h>
#include <cstdint>
#include <math.h>

#define NA 4096
#define NB 4096
#define D  256
#define H  4
#define DK 64
#define BM 128
#define BN 32
#define KSPLIT 3
#define ITER_S0 43                 // splits get 43/43/42 iters (128 total)
#define LOG2E 1.4426950408889634f

// ---------------- global scratch (no cudaMalloc allowed) ----------------
__device__ __half g_Q[H * NA * DK];        // pre-scaled by 1/8
__device__ __half g_K[H * NB * DK];
__device__ __half g_Vt[H * DK * NB];       // transposed [head][d][b]
__device__ __half g_ew[(size_t)NA * NB];   // mask ? exp(sani(w)) : 0
__device__ float g_pO[KSPLIT * H * NA * DK];   // partial O
__device__ float g_pl[KSPLIT * H * NA];        // partial row sums
__device__ int   g_mask_is_i32;

typedef unsigned long long u64;
typedef unsigned int u32;

// smem layout (bytes):
//   Q      @0      16384
//   KV[b]  @16384 + b*12288   (K 4096 @+0, Vt 8192 @+4096)
//   E[b]   @40960 + b*10240   (128 rows x 80B pitch; 64B data)
#define SMQ    0
#define SMKV(b) (16384 + (b) * 12288)
#define SME(b)  (40960 + (b) * 10240)
#define SM_TOTAL 61440

// ---------------- helpers ----------------
__device__ __forceinline__ u64 pack2(float x, float y) {
    u64 r; asm("mov.b64 %0, {%1,%2};" : "=l"(r) : "f"(x), "f"(y)); return r;
}
__device__ __forceinline__ void unpack2(u64 v, float& x, float& y) {
    asm("mov.b64 {%0,%1}, %2;" : "=f"(x), "=f"(y) : "l"(v));
}
__device__ __forceinline__ u64 fma2(u64 a, u64 b, u64 c) {
    u64 d; asm("fma.rn.f32x2 %0, %1, %2, %3;" : "=l"(d) : "l"(a), "l"(b), "l"(c)); return d;
}
__device__ __forceinline__ float sani(float x) {
    if (isnan(x)) return 0.0f;
    if (isinf(x)) return x > 0.0f ? 1.0f : -1.0f;
    return x;
}
__device__ __forceinline__ float ex2f(float x) {
    float y; asm("ex2.approx.ftz.f32 %0, %1;" : "=f"(y) : "f"(x)); return y;
}
__device__ __forceinline__ u32 smem_u32(const void* p) {
    u32 a; asm("{ .reg .u64 t; cvta.to.shared.u64 t, %1; cvt.u32.u64 %0, t; }" : "=r"(a) : "l"(p));
    return a;
}
__device__ __forceinline__ void cp16(u32 dst, const void* src) {
    asm volatile("cp.async.cg.shared.global [%0], [%1], 16;" :: "r"(dst), "l"(src));
}
__device__ __forceinline__ void cp_commit() { asm volatile("cp.async.commit_group;"); }
__device__ __forceinline__ void cp_wait0()  { asm volatile("cp.async.wait_group 0;"); }

__device__ __forceinline__ void ldsm4(u32 addr, u32& r0, u32& r1, u32& r2, u32& r3) {
    asm volatile("ldmatrix.sync.aligned.m8n8.x4.shared.b16 {%0,%1,%2,%3}, [%4];"
                 : "=r"(r0), "=r"(r1), "=r"(r2), "=r"(r3) : "r"(addr));
}
__device__ __forceinline__ void mma16816(float* c, u32 a0, u32 a1, u32 a2, u32 a3, u32 b0, u32 b1) {
    asm volatile(
        "mma.sync.aligned.m16n8k16.row.col.f32.f16.f16.f32 "
        "{%0,%1,%2,%3}, {%4,%5,%6,%7}, {%8,%9}, {%0,%1,%2,%3};"
        : "+f"(c[0]), "+f"(c[1]), "+f"(c[2]), "+f"(c[3])
        : "r"(a0), "r"(a1), "r"(a2), "r"(a3), "r"(b0), "r"(b1));
}
// pack two floats to f16x2, first arg in low 16 bits
__device__ __forceinline__ u32 packhf(float lo, float hi) {
    u32 d; asm("cvt.rn.f16x2.f32 %0, %1, %2;" : "=r"(d) : "f"(hi), "f"(lo)); return d;
}
__device__ __forceinline__ u32 swaddr(u32 base, int row, int colhalf) {
    int ch = colhalf >> 3;
    return base + row * 128 + (((ch ^ (row & 7)) << 4));
}

// ---------------- mask dtype detector ----------------
__global__ void detect_mask_kernel(const unsigned* __restrict__ m) {
    __shared__ int bad;
    if (threadIdx.x == 0) bad = 0;
    __syncthreads();
    for (int i = threadIdx.x; i < 4096; i += blockDim.x)
        if (m[i] > 1u) bad = 1;
    __syncthreads();
    if (threadIdx.x == 0) g_mask_is_i32 = bad ? 0 : 1;
}

// ---------------- merged projections + E = mask ? exp(sani(w)) : 0 ----------------
#define PSTRIDE 68
__global__ __launch_bounds__(256) void projpack_kernel(
    const float* __restrict__ a_z, const float* __restrict__ bv_z,
    const float* __restrict__ Wq, const float* __restrict__ Wk,
    const float* __restrict__ Wv, const float* __restrict__ weight,
    const unsigned char* __restrict__ m8, const int* __restrict__ m32)
{
    const int z = blockIdx.z;
    const int tid = threadIdx.x;

    if (z == 3) {
        // one thread = 32 cols of one row
        const int w = (blockIdx.x * 32 + blockIdx.y) * 256 + tid;  // 0..524287
        const int row = w >> 7, wc = w & 127;
        const size_t off = (size_t)row * NB + wc * 32;
        const float* wp = weight + off;
        u32 outw[16];
        if (g_mask_is_i32) {
#pragma unroll
            for (int t = 0; t < 8; t++) {
                int4 m = *(const int4*)(m32 + off + t * 4);
                float4 wv = *(const float4*)(wp + t * 4);
                float e0 = m.x ? ex2f(sani(wv.x) * LOG2E) : 0.0f;
                float e1 = m.y ? ex2f(sani(wv.y) * LOG2E) : 0.0f;
                float e2 = m.z ? ex2f(sani(wv.z) * LOG2E) : 0.0f;
                float e3 = m.w ? ex2f(sani(wv.w) * LOG2E) : 0.0f;
                outw[t * 2 + 0] = packhf(e0, e1);
                outw[t * 2 + 1] = packhf(e2, e3);
            }
        } else {
#pragma unroll
            for (int t = 0; t < 8; t++) {
                uchar4 m = *(const uchar4*)(m8 + off + t * 4);
                float4 wv = *(const float4*)(wp + t * 4);
                float e0 = m.x ? ex2f(sani(wv.x) * LOG2E) : 0.0f;
                float e1 = m.y ? ex2f(sani(wv.y) * LOG2E) : 0.0f;
                float e2 = m.z ? ex2f(sani(wv.z) * LOG2E) : 0.0f;
                float e3 = m.w ? ex2f(sani(wv.w) * LOG2E) : 0.0f;
                outw[t * 2 + 0] = packhf(e0, e1);
                outw[t * 2 + 1] = packhf(e2, e3);
            }
        }
        uint4* dst = (uint4*)(g_ew + off);
#pragma unroll
        for (int t = 0; t < 4; t++)
            dst[t] = make_uint4(outw[4 * t], outw[4 * t + 1], outw[4 * t + 2], outw[4 * t + 3]);
        return;
    }

    if (blockIdx.y >= 4) return;

    __shared__ float Xs[32][PSTRIDE];
    __shared__ float Ws[32][PSTRIDE];

    const float* X = (z == 0) ? a_z : bv_z;
    const float* W = (z == 0) ? Wq : (z == 1) ? Wk : Wv;
    const float outscale = (z == 0) ? 0.125f : 1.0f;

    const int tx = tid & 15, ty = tid >> 4;
    const int r0 = blockIdx.x * 64, c0 = blockIdx.y * 64;

    u64 acc[2][4];
#pragma unroll
    for (int p = 0; p < 2; p++)
#pragma unroll
        for (int j = 0; j < 4; j++) acc[p][j] = 0ull;

    for (int k0 = 0; k0 < D; k0 += 32) {
        __syncthreads();
#pragma unroll
        for (int s = 0; s < 2; s++) {
            int idx = tid * 2 + s;
            int row = idx >> 3;
            int k4  = (idx & 7) * 4;
            float4 v = *(const float4*)&X[(size_t)(r0 + row) * D + k0 + k4];
            Xs[k4 + 0][row] = sani(v.x);
            Xs[k4 + 1][row] = sani(v.y);
            Xs[k4 + 2][row] = sani(v.z);
            Xs[k4 + 3][row] = sani(v.w);
            float4 w = *(const float4*)&W[(size_t)(c0 + row) * D + k0 + k4];
            Ws[k4 + 0][row] = w.x;
            Ws[k4 + 1][row] = w.y;
            Ws[k4 + 2][row] = w.z;
            Ws[k4 + 3][row] = w.w;
        }
        __syncthreads();
#pragma unroll 8
        for (int kk = 0; kk < 32; kk++) {
            const u64* ap = (const u64*)&Xs[kk][ty * 4];
            u64 a0 = ap[0], a1 = ap[1];
            float4 b = *(const float4*)&Ws[kk][tx * 4];
            u64 b0 = pack2(b.x, b.x), b1 = pack2(b.y, b.y);
            u64 b2 = pack2(b.z, b.z), b3 = pack2(b.w, b.w);
            acc[0][0] = fma2(a0, b0, acc[0][0]);
            acc[0][1] = fma2(a0, b1, acc[0][1]);
            acc[0][2] = fma2(a0, b2, acc[0][2]);
            acc[0][3] = fma2(a0, b3, acc[0][3]);
            acc[1][0] = fma2(a1, b0, acc[1][0]);
            acc[1][1] = fma2(a1, b1, acc[1][1]);
            acc[1][2] = fma2(a1, b2, acc[1][2]);
            acc[1][3] = fma2(a1, b3, acc[1][3]);
        }
    }
#pragma unroll
    for (int p = 0; p < 2; p++)
#pragma unroll
        for (int j = 0; j < 4; j++) {
            float x, y; unpack2(acc[p][j], x, y);
            x *= outscale; y *= outscale;
            const int rr = r0 + ty * 4 + p * 2;
            const int c  = c0 + tx * 4 + j;
            const int hd = c >> 6, hc = c & 63;
            __half xh = __float2half(x);
            __half yh = __float2half(y);
            if (z == 0) {
                size_t o = ((size_t)hd * NA + rr) * DK + hc;
                g_Q[o] = xh;
                g_Q[o + DK] = yh;
            } else if (z == 1) {
                size_t o = ((size_t)hd * NB + rr) * DK + hc;
                g_K[o] = xh;
                g_K[o + DK] = yh;
            } else {
                size_t o = ((size_t)hd * DK + hc) * NB + rr;
                g_Vt[o] = xh;
                g_Vt[o + 1] = yh;
            }
        }
}

// ---------------- async tile loads (128 threads) ----------------
__device__ __forceinline__ void load_kve_async(u32 sb, int buf, int head, int b0,
                                               int q0, int tid) {
    const u32 base = sb + SMKV(buf);
#pragma unroll
    for (int s = 0; s < 2; s++) {   // K: 32 rows x 8 chunks (swizzled)
        int idx = tid + s * 128;
        int row = idx >> 3, ch = idx & 7;
        const __half* src = g_K + ((size_t)head * NB + b0 + row) * DK + ch * 8;
        cp16(base + row * 128 + ((ch ^ (row & 7)) << 4), src);
    }
#pragma unroll
    for (int s = 0; s < 2; s++) {   // Vt: 64 rows x 4 chunks (swizzled)
        int idx = tid + s * 128;
        int row = idx >> 2, ch = idx & 3;
        const __half* src = g_Vt + ((size_t)head * DK + row) * NB + b0 + ch * 8;
        cp16(base + 4096 + row * 128 + ((ch ^ (row & 7)) << 4), src);
    }
    const u32 ebase = sb + SME(buf);
#pragma unroll
    for (int s = 0; s < 4; s++) {   // E: 128 rows x 4 chunks, 80B pitch (no swizzle)
        int idx = tid + s * 128;
        int row = idx >> 2, ch = idx & 3;
        const __half* src = g_ew + (size_t)(q0 + row) * NB + b0 + ch * 8;
        cp16(ebase + row * 80 + ch * 16, src);
    }
}

// ---------------- fused flash attention: 4 warps M=32, folded-E softmax ----------------
__global__ __launch_bounds__(128, 3) void attn_kernel()
{
    extern __shared__ char smch[];
    const u32 sb = smem_u32(smch);
    const int tid = threadIdx.x;
    const int w = tid >> 5, lane = tid & 31;
    const int g = lane >> 2, qd = lane & 3;
    const int head = blockIdx.x;
    const int q0 = blockIdx.y * BM;
    const int split = blockIdx.z;
    const int istart = split * ITER_S0;
    const int niter = (split == 2) ? 42 : ITER_S0;

    const int aRow = (lane & 7) + ((lane >> 3) & 1) * 8;
    const int aCol = ((lane >> 4) & 1) * 8;
    const int bRow = (lane & 7) + ((lane >> 4) & 1) * 8;
    const int bCol = ((lane >> 3) & 1) * 8;

    // ---- prologue: Q + KVE buf0 ----
#pragma unroll
    for (int s = 0; s < 8; s++) {
        int idx = tid + s * 128;
        int row = idx >> 3;
        int ch  = idx & 7;
        const __half* src = g_Q + ((size_t)head * NA + q0 + row) * DK + ch * 8;
        cp16(sb + SMQ + row * 128 + ((ch ^ (row & 7)) << 4), src);
    }
    load_kve_async(sb, 0, head, istart * BN, q0, tid);
    cp_commit();
    cp_wait0();
    __syncthreads();

    // ---- Q fragments: 2 row-tiles x 4 k-tiles ----
    const int r0 = w * 32;
    u32 qh[2][4][4];
#pragma unroll
    for (int rt = 0; rt < 2; rt++)
#pragma unroll
        for (int kt = 0; kt < 4; kt++)
            ldsm4(swaddr(sb + SMQ, r0 + rt * 16 + aRow, kt * 16 + aCol),
                  qh[rt][kt][0], qh[rt][kt][1], qh[rt][kt][2], qh[rt][kt][3]);

    float oacc[2][8][4];
#pragma unroll
    for (int rt = 0; rt < 2; rt++)
#pragma unroll
        for (int j = 0; j < 8; j++)
#pragma unroll
            for (int e = 0; e < 4; e++) oacc[rt][j][e] = 0.0f;
    float lsum[2][2] = {{0.f, 0.f}, {0.f, 0.f}};

    const int rbase = q0 + r0 + g;
    const int wrow0 = r0 + g;
    const __half2 CHI2 = __float2half2_rn(22026.465f);    // e^10
    const __half2 CLO2 = __float2half2_rn(4.5399930e-5f); // e^-10

    for (int i = 0; i < niter; i++) {
        const int cur = i & 1;

        if (i + 1 < niter) {
            load_kve_async(sb, cur ^ 1, head, (istart + i + 1) * BN, q0, tid);
            cp_commit();
        }

        // ---- S = (Q/8) K^T : shared K frags across both row-tiles ----
        float sacc[2][4][4];
#pragma unroll
        for (int rt = 0; rt < 2; rt++)
#pragma unroll
            for (int j = 0; j < 4; j++)
#pragma unroll
                for (int e = 0; e < 4; e++) sacc[rt][j][e] = 0.0f;

        const u32 kB = sb + SMKV(cur);
#pragma unroll
        for (int kt = 0; kt < 4; kt++) {
#pragma unroll
            for (int jp = 0; jp < 2; jp++) {
                u32 k0r, k1r, k2r, k3r;
                ldsm4(swaddr(kB, jp * 16 + bRow, kt * 16 + bCol), k0r, k1r, k2r, k3r);
#pragma unroll
                for (int rt = 0; rt < 2; rt++) {
                    mma16816(sacc[rt][2 * jp],     qh[rt][kt][0], qh[rt][kt][1], qh[rt][kt][2], qh[rt][kt][3], k0r, k1r);
                    mma16816(sacc[rt][2 * jp + 1], qh[rt][kt][0], qh[rt][kt][1], qh[rt][kt][2], qh[rt][kt][3], k2r, k3r);
                }
            }
        }

        // ---- softmax: P = clamp(exp(s)*E, e^-10, e^10); masked E=0 -> P=e^-10 ----
        const int eoff = SME(cur);
        u32 phf[2][4][2];
#pragma unroll
        for (int rt = 0; rt < 2; rt++) {
            const int rA = wrow0 + rt * 16;
#pragma unroll
            for (int j = 0; j < 4; j++) {
                u32 eA  = *(const u32*)(smch + eoff + rA * 80 + j * 16 + qd * 4);
                u32 eBv = *(const u32*)(smch + eoff + (rA + 8) * 80 + j * 16 + qd * 4);
                float p0 = ex2f(sacc[rt][j][0] * LOG2E);
                float p1 = ex2f(sacc[rt][j][1] * LOG2E);
                float p2 = ex2f(sacc[rt][j][2] * LOG2E);
                float p3 = ex2f(sacc[rt][j][3] * LOG2E);
                u32 psA = packhf(p0, p1);
                u32 psB = packhf(p2, p3);
                __half2 PA = __hmul2(*(const __half2*)&psA, *(const __half2*)&eA);
                __half2 PB = __hmul2(*(const __half2*)&psB, *(const __half2*)&eBv);
                PA = __hmax2(__hmin2(PA, CHI2), CLO2);
                PB = __hmax2(__hmin2(PB, CHI2), CLO2);
                float2 fA = __half22float2(PA);
                float2 fB = __half22float2(PB);
                lsum[rt][0] += fA.x + fA.y;
                lsum[rt][1] += fB.x + fB.y;
                phf[rt][j][0] = *(const u32*)&PA;
                phf[rt][j][1] = *(const u32*)&PB;
            }
        }

        // ---- O += P @ V : shared V frags across both row-tiles ----
        const u32 vB = sb + SMKV(cur) + 4096;
#pragma unroll
        for (int kt = 0; kt < 2; kt++) {
#pragma unroll
            for (int jp = 0; jp < 4; jp++) {
                u32 v0r, v1r, v2r, v3r;
                ldsm4(swaddr(vB, jp * 16 + bRow, kt * 16 + bCol), v0r, v1r, v2r, v3r);
#pragma unroll
                for (int rt = 0; rt < 2; rt++) {
                    u32 a0 = phf[rt][2 * kt][0], a1 = phf[rt][2 * kt][1];
                    u32 a2 = phf[rt][2 * kt + 1][0], a3 = phf[rt][2 * kt + 1][1];
                    mma16816(oacc[rt][2 * jp],     a0, a1, a2, a3, v0r, v1r);
                    mma16816(oacc[rt][2 * jp + 1], a0, a1, a2, a3, v2r, v3r);
                }
            }
        }

        if (i + 1 < niter) cp_wait0();
        __syncthreads();
    }

    // ---- epilogue: partial O + partial l (additive across splits) ----
    const size_t po = ((size_t)(split * H + head) * NA);
#pragma unroll
    for (int rt = 0; rt < 2; rt++) {
        float lA = lsum[rt][0], lB = lsum[rt][1];
        lA += __shfl_xor_sync(0xffffffffu, lA, 1);
        lA += __shfl_xor_sync(0xffffffffu, lA, 2);
        lB += __shfl_xor_sync(0xffffffffu, lB, 1);
        lB += __shfl_xor_sync(0xffffffffu, lB, 2);
        const int rGA = rbase + rt * 16;
        const int rGB = rGA + 8;
        if (qd == 0) {
            g_pl[po + rGA] = lA;
            g_pl[po + rGB] = lB;
        }
        float* pA = g_pO + (po + rGA) * DK + qd * 2;
        float* pB = g_pO + (po + rGB) * DK + qd * 2;
#pragma unroll
        for (int j = 0; j < 8; j++) {
            *(float2*)(pA + j * 8) = make_float2(oacc[rt][j][0], oacc[rt][j][1]);
            *(float2*)(pB + j * 8) = make_float2(oacc[rt][j][2], oacc[rt][j][3]);
        }
    }
}

// ---------------- finalize: combine splits, head mean, influence ----------------
__global__ __launch_bounds__(256) void finalize_kernel(float* __restrict__ out)
{
    int idx = blockIdx.x * blockDim.x + threadIdx.x;   // 0..65535
    if (idx < NA * DK / 4) {
        const int row = idx >> 4;
        const int c4 = (idx & 15) * 4;
        float ax = 0.f, ay = 0.f, az = 0.f, aw = 0.f;
#pragma unroll
        for (int h = 0; h < H; h++) {
            float ox = 0.f, oy = 0.f, oz = 0.f, ow = 0.f, l = 0.f;
#pragma unroll
            for (int s = 0; s < KSPLIT; s++) {
                const float4 v = *(const float4*)&g_pO[((size_t)(s * H + h) * NA + row) * DK + c4];
                ox += v.x; oy += v.y; oz += v.z; ow += v.w;
                l += g_pl[(size_t)(s * H + h) * NA + row];
            }
            const float inv = 1.0f / l;
            ax += ox * inv; ay += oy * inv; az += oz * inv; aw += ow * inv;
        }
        *(float4*)&out[(size_t)row * DK + c4] =
            make_float4(ax * 0.25f, ay * 0.25f, az * 0.25f, aw * 0.25f);
    }
    if (idx < NA) {
        out[NA * DK + idx] = 1.0f;   // softmax rows sum to exactly 1
    }
}

// ---------------- launch ----------------
extern "C" void kernel_launch(void* const* d_in, const int* in_sizes, int n_in,
                              void* d_out, int out_size)
{
    const float* a_z    = (const float*)d_in[0];
    const float* bv_z   = (const float*)d_in[1];
    const void*  maskp  = d_in[2];
    const float* weight = (const float*)d_in[3];
    const float* Wq     = (const float*)d_in[4];
    const float* Wk     = (const float*)d_in[5];
    const float* Wv     = (const float*)d_in[6];
    float* out = (float*)d_out;

    cudaFuncSetAttribute(attn_kernel, cudaFuncAttributeMaxDynamicSharedMemorySize, SM_TOTAL);

    detect_mask_kernel<<<1, 256>>>((const unsigned*)maskp);
    projpack_kernel<<<dim3(64, 32, 4), 256>>>(a_z, bv_z, Wq, Wk, Wv, weight,
        (const unsigned char*)maskp, (const int*)maskp);
    attn_kernel<<<dim3(H, NA / BM, KSPLIT), 128, SM_TOTAL>>>();
    finalize_kernel<<<(NA * DK / 4 + 255) / 256, 256>>>(out);
}

// round 14
// speedup vs baseline: 1.8747x; 1.2071x over previous
#include <cuda_runtime.h>
#include <cuda_fp16.h>
#include <cstdint>
#include <math.h>

#define NA 4096
#define NB 4096
#define D  256
#define H  4
#define DK 64
#define BM 128
#define BN 32
#define KSPLIT 3
#define ITER_S0 43                 // splits get 43/43/42 iters (128 total)
#define LOG2E 1.4426950408889634f

// ---------------- global scratch (no cudaMalloc allowed) ----------------
__device__ __half g_Q[H * NA * DK];        // pre-scaled by 1/8
__device__ __half g_K[H * NB * DK];
__device__ __half g_Vt[H * DK * NB];       // transposed [head][d][b]
__device__ float g_pO[KSPLIT * H * NA * DK];   // partial O
__device__ float g_pl[KSPLIT * H * NA];        // partial row sums
__device__ unsigned g_mbits[NA * (NB / 32)];   // bit-packed mask

typedef unsigned long long u64;
typedef unsigned int u32;

// attn smem layout (bytes):
//   Q      @0      16384
//   KV[b]  @16384 + b*12288   (K 4096 @+0, Vt 8192 @+4096)
//   W[b]   @40960 + b*16384   (128 rows x 128B, swizzled)
#define SMQ    0
#define SMKV(b) (16384 + (b) * 12288)
#define SMW(b)  (40960 + (b) * 16384)
#define SM_TOTAL 73728

// ---------------- helpers ----------------
__device__ __forceinline__ float sani(float x) {
    if (isnan(x)) return 0.0f;
    if (isinf(x)) return x > 0.0f ? 1.0f : -1.0f;
    return x;
}
__device__ __forceinline__ float ex2f(float x) {
    float y; asm("ex2.approx.ftz.f32 %0, %1;" : "=f"(y) : "f"(x)); return y;
}
__device__ __forceinline__ u32 smem_u32(const void* p) {
    u32 a; asm("{ .reg .u64 t; cvta.to.shared.u64 t, %1; cvt.u32.u64 %0, t; }" : "=r"(a) : "l"(p));
    return a;
}
__device__ __forceinline__ void cp16(u32 dst, const void* src) {
    asm volatile("cp.async.cg.shared.global [%0], [%1], 16;" :: "r"(dst), "l"(src));
}
__device__ __forceinline__ void cp_commit() { asm volatile("cp.async.commit_group;"); }
__device__ __forceinline__ void cp_wait0()  { asm volatile("cp.async.wait_group 0;"); }

__device__ __forceinline__ void ldsm4(u32 addr, u32& r0, u32& r1, u32& r2, u32& r3) {
    asm volatile("ldmatrix.sync.aligned.m8n8.x4.shared.b16 {%0,%1,%2,%3}, [%4];"
                 : "=r"(r0), "=r"(r1), "=r"(r2), "=r"(r3) : "r"(addr));
}
__device__ __forceinline__ void mma16816(float* c, u32 a0, u32 a1, u32 a2, u32 a3, u32 b0, u32 b1) {
    asm volatile(
        "mma.sync.aligned.m16n8k16.row.col.f32.f16.f16.f32 "
        "{%0,%1,%2,%3}, {%4,%5,%6,%7}, {%8,%9}, {%0,%1,%2,%3};"
        : "+f"(c[0]), "+f"(c[1]), "+f"(c[2]), "+f"(c[3])
        : "r"(a0), "r"(a1), "r"(a2), "r"(a3), "r"(b0), "r"(b1));
}
// pack two floats to f16x2, first arg in low 16 bits
__device__ __forceinline__ u32 packhf(float lo, float hi) {
    u32 d; asm("cvt.rn.f16x2.f32 %0, %1, %2;" : "=r"(d) : "f"(hi), "f"(lo)); return d;
}
__device__ __forceinline__ u32 swaddr(u32 base, int row, int colhalf) {
    int ch = colhalf >> 3;
    return base + row * 128 + (((ch ^ (row & 7)) << 4));
}

// ---------------- tensor-core projections + fused mask bitpack ----------------
// grid (32, 8, 4), block 128.
// z<3: proj planes (by<4 only): out tile 128 rows x 64 cols, K=256 in 8 steps.
// z==3: mask bitpack with per-thread dtype detection (all 8 by).
__global__ __launch_bounds__(128) void projtc_kernel(
    const float* __restrict__ a_z, const float* __restrict__ bv_z,
    const float* __restrict__ Wq, const float* __restrict__ Wk,
    const float* __restrict__ Wv,
    const unsigned char* __restrict__ m8, const int* __restrict__ m32)
{
    const int z = blockIdx.z;
    const int tid = threadIdx.x;

    if (z == 3) {
        // ---- bitpack: 32768 threads, 16 output words (512 cols) each ----
        const int t = (blockIdx.x * 8 + blockIdx.y) * 128 + tid;  // 0..32767
        const int row = t >> 3;
        const int colbase = (t & 7) * 512;
        const size_t off = (size_t)row * NB + colbase;
        // per-thread dtype detection: scan first 32 words as i32
        const int4* p32 = (const int4*)(m32 + off);
        u32 bad = 0;
#pragma unroll
        for (int s = 0; s < 8; s++) {
            int4 v = p32[s];
            bad |= ((u32)v.x > 1u) | ((u32)v.y > 1u) | ((u32)v.z > 1u) | ((u32)v.w > 1u);
        }
        u32 bits[16];
        if (!bad) {
            // i32 bools
#pragma unroll
            for (int wd = 0; wd < 16; wd++) {
                u32 b = 0;
#pragma unroll
                for (int s = 0; s < 8; s++) {
                    int4 v = p32[wd * 8 + s];
                    b |= (v.x != 0 ? 1u : 0u) << (4 * s + 0);
                    b |= (v.y != 0 ? 1u : 0u) << (4 * s + 1);
                    b |= (v.z != 0 ? 1u : 0u) << (4 * s + 2);
                    b |= (v.w != 0 ? 1u : 0u) << (4 * s + 3);
                }
                bits[wd] = b;
            }
        } else {
            // u8 bools
            const uint4* p8 = (const uint4*)(m8 + off);
#pragma unroll
            for (int wd = 0; wd < 16; wd++) {
                u32 b = 0;
#pragma unroll
                for (int s = 0; s < 2; s++) {
                    uint4 v = p8[wd * 2 + s];
                    u32 wds4[4] = {v.x, v.y, v.z, v.w};
#pragma unroll
                    for (int q = 0; q < 4; q++)
#pragma unroll
                        for (int bq = 0; bq < 4; bq++)
                            b |= (((wds4[q] >> (8 * bq)) & 0xffu) ? 1u : 0u) << (s * 16 + q * 4 + bq);
                }
                bits[wd] = b;
            }
        }
        uint4* dst = (uint4*)(g_mbits + (size_t)row * 128 + (t & 7) * 16);
#pragma unroll
        for (int s = 0; s < 4; s++)
            dst[s] = make_uint4(bits[4 * s], bits[4 * s + 1], bits[4 * s + 2], bits[4 * s + 3]);
        return;
    }

    if (blockIdx.y >= 4) return;

    // ---- tensor-core proj: As[128][80B], Bs[64][80B] (fp16, conflict-free pitch) ----
    __shared__ char psm[128 * 80 + 64 * 80];
    const u32 sA = smem_u32(psm);
    const u32 sB = sA + 128 * 80;

    const float* X = (z == 0) ? a_z : bv_z;
    const float* W = (z == 0) ? Wq : (z == 1) ? Wk : Wv;
    const float outscale = (z == 0) ? 0.125f : 1.0f;

    const int w = tid >> 5, lane = tid & 31;
    const int g = lane >> 2, qd = lane & 3;
    const int r0g = blockIdx.x * 128;
    const int c0 = blockIdx.y * 64;

    const int aRow = (lane & 7) + ((lane >> 3) & 1) * 8;
    const int aCol = ((lane >> 4) & 1) * 8;
    const int bRow = (lane & 7) + ((lane >> 4) & 1) * 8;
    const int bCol = ((lane >> 3) & 1) * 8;

    float oacc[2][8][4];
#pragma unroll
    for (int rt = 0; rt < 2; rt++)
#pragma unroll
        for (int j = 0; j < 8; j++)
#pragma unroll
            for (int e = 0; e < 4; e++) oacc[rt][j][e] = 0.0f;

    for (int k0 = 0; k0 < D; k0 += 32) {
        __syncthreads();
        // A: 128 rows x 32 k (fp32 -> sanitized fp16)
#pragma unroll
        for (int s = 0; s < 8; s++) {
            int c = tid + s * 128;          // 0..1023
            int row = c >> 3, part = c & 7;
            float4 v = *(const float4*)&X[(size_t)(r0g + row) * D + k0 + part * 4];
            u32 lo = packhf(sani(v.x), sani(v.y));
            u32 hi = packhf(sani(v.z), sani(v.w));
            *(uint2*)(psm + row * 80 + part * 8) = make_uint2(lo, hi);
        }
        // B: 64 rows (out cols) x 32 k
#pragma unroll
        for (int s = 0; s < 4; s++) {
            int c = tid + s * 128;          // 0..511
            int row = c >> 3, part = c & 7;
            float4 v = *(const float4*)&W[(size_t)(c0 + row) * D + k0 + part * 4];
            u32 lo = packhf(v.x, v.y);
            u32 hi = packhf(v.z, v.w);
            *(uint2*)(psm + 128 * 80 + row * 80 + part * 8) = make_uint2(lo, hi);
        }
        __syncthreads();

        u32 af[2][2][4];
#pragma unroll
        for (int rt = 0; rt < 2; rt++)
#pragma unroll
            for (int kt = 0; kt < 2; kt++)
                ldsm4(sA + (w * 32 + rt * 16 + aRow) * 80 + kt * 32 + (aCol ? 16 : 0),
                      af[rt][kt][0], af[rt][kt][1], af[rt][kt][2], af[rt][kt][3]);

#pragma unroll
        for (int kt = 0; kt < 2; kt++) {
#pragma unroll
            for (int jp = 0; jp < 4; jp++) {
                u32 b0, b1, b2, b3;
                ldsm4(sB + (jp * 16 + bRow) * 80 + kt * 32 + (bCol ? 16 : 0), b0, b1, b2, b3);
#pragma unroll
                for (int rt = 0; rt < 2; rt++) {
                    mma16816(oacc[rt][2 * jp],     af[rt][kt][0], af[rt][kt][1], af[rt][kt][2], af[rt][kt][3], b0, b1);
                    mma16816(oacc[rt][2 * jp + 1], af[rt][kt][0], af[rt][kt][1], af[rt][kt][2], af[rt][kt][3], b2, b3);
                }
            }
        }
    }

    // ---- epilogue: scale, cvt fp16, store head-split ----
#pragma unroll
    for (int rt = 0; rt < 2; rt++) {
        const int rowA = r0g + w * 32 + rt * 16 + g;
        const int rowB = rowA + 8;
#pragma unroll
        for (int j = 0; j < 8; j++) {
            const int c = c0 + j * 8 + qd * 2;
            const int hd = c >> 6, hc = c & 63;
            float v0 = oacc[rt][j][0] * outscale, v1 = oacc[rt][j][1] * outscale;
            float v2 = oacc[rt][j][2] * outscale, v3 = oacc[rt][j][3] * outscale;
            if (z == 0) {
                *(u32*)&g_Q[((size_t)hd * NA + rowA) * DK + hc] = packhf(v0, v1);
                *(u32*)&g_Q[((size_t)hd * NA + rowB) * DK + hc] = packhf(v2, v3);
            } else if (z == 1) {
                *(u32*)&g_K[((size_t)hd * NB + rowA) * DK + hc] = packhf(v0, v1);
                *(u32*)&g_K[((size_t)hd * NB + rowB) * DK + hc] = packhf(v2, v3);
            } else {
                g_Vt[((size_t)hd * DK + hc) * NB + rowA]     = __float2half(v0);
                g_Vt[((size_t)hd * DK + hc + 1) * NB + rowA] = __float2half(v1);
                g_Vt[((size_t)hd * DK + hc) * NB + rowB]     = __float2half(v2);
                g_Vt[((size_t)hd * DK + hc + 1) * NB + rowB] = __float2half(v3);
            }
        }
    }
}

// ---------------- async tile loads (128 threads) ----------------
__device__ __forceinline__ void load_kvw_async(u32 sb, int buf, int head, int b0,
                                               const float* __restrict__ weight,
                                               int q0, int tid) {
    const u32 base = sb + SMKV(buf);
#pragma unroll
    for (int s = 0; s < 2; s++) {   // K: 32 rows x 8 chunks
        int idx = tid + s * 128;
        int row = idx >> 3, ch = idx & 7;
        const __half* src = g_K + ((size_t)head * NB + b0 + row) * DK + ch * 8;
        cp16(base + row * 128 + ((ch ^ (row & 7)) << 4), src);
    }
#pragma unroll
    for (int s = 0; s < 2; s++) {   // Vt: 64 rows x 4 chunks
        int idx = tid + s * 128;
        int row = idx >> 2, ch = idx & 3;
        const __half* src = g_Vt + ((size_t)head * DK + row) * NB + b0 + ch * 8;
        cp16(base + 4096 + row * 128 + ((ch ^ (row & 7)) << 4), src);
    }
    const u32 wbase = sb + SMW(buf);
#pragma unroll
    for (int s = 0; s < 8; s++) {   // W: 128 rows x 8 chunks (32 floats/row)
        int idx = tid + s * 128;
        int row = idx >> 3, ch = idx & 7;
        const float* src = weight + (size_t)(q0 + row) * NB + b0 + ch * 4;
        cp16(wbase + row * 128 + ((ch ^ (row & 7)) << 4), src);
    }
}

// ---------------- fused flash attention: 4 warps, M=32/warp, W in smem ----------------
__global__ __launch_bounds__(128, 3) void attn_kernel(const float* __restrict__ weight)
{
    extern __shared__ char smch[];
    const u32 sb = smem_u32(smch);
    const int tid = threadIdx.x;
    const int w = tid >> 5, lane = tid & 31;
    const int g = lane >> 2, qd = lane & 3;
    const int head = blockIdx.x;
    const int q0 = blockIdx.y * BM;
    const int split = blockIdx.z;
    const int istart = split * ITER_S0;
    const int niter = (split == 2) ? 42 : ITER_S0;

    const int aRow = (lane & 7) + ((lane >> 3) & 1) * 8;
    const int aCol = ((lane >> 4) & 1) * 8;
    const int bRow = (lane & 7) + ((lane >> 4) & 1) * 8;
    const int bCol = ((lane >> 3) & 1) * 8;

    // ---- prologue: Q + KV/W buf0 ----
#pragma unroll
    for (int s = 0; s < 8; s++) {
        int idx = tid + s * 128;
        int row = idx >> 3;
        int ch  = idx & 7;
        const __half* src = g_Q + ((size_t)head * NA + q0 + row) * DK + ch * 8;
        cp16(sb + SMQ + row * 128 + ((ch ^ (row & 7)) << 4), src);
    }
    load_kvw_async(sb, 0, head, istart * BN, weight, q0, tid);
    cp_commit();
    cp_wait0();
    __syncthreads();

    // ---- Q fragments: 2 row-tiles x 4 k-tiles ----
    const int r0 = w * 32;
    u32 qh[2][4][4];
#pragma unroll
    for (int rt = 0; rt < 2; rt++)
#pragma unroll
        for (int kt = 0; kt < 4; kt++)
            ldsm4(swaddr(sb + SMQ, r0 + rt * 16 + aRow, kt * 16 + aCol),
                  qh[rt][kt][0], qh[rt][kt][1], qh[rt][kt][2], qh[rt][kt][3]);

    float oacc[2][8][4];
#pragma unroll
    for (int rt = 0; rt < 2; rt++)
#pragma unroll
        for (int j = 0; j < 8; j++)
#pragma unroll
            for (int e = 0; e < 4; e++) oacc[rt][j][e] = 0.0f;
    float lsum[2][2] = {{0.f, 0.f}, {0.f, 0.f}};

    const int rbase = q0 + r0 + g;
    const unsigned* mbase = g_mbits + (size_t)rbase * (NB / 32) + istart;
    const int wrow0 = r0 + g;

    for (int i = 0; i < niter; i++) {
        const int cur = i & 1;

        if (i + 1 < niter) {
            load_kvw_async(sb, cur ^ 1, head, (istart + i + 1) * BN, weight, q0, tid);
            cp_commit();
        }

        // ---- packed mask for 4 rows ----
        u32 mr[2][2];
#pragma unroll
        for (int rt = 0; rt < 2; rt++) {
            mr[rt][0] = mbase[(rt * 16 + 0) * (NB / 32) + i];
            mr[rt][1] = mbase[(rt * 16 + 8) * (NB / 32) + i];
        }

        // ---- S = (Q/8) K^T : shared K frags across both row-tiles ----
        float sacc[2][4][4];
#pragma unroll
        for (int rt = 0; rt < 2; rt++)
#pragma unroll
            for (int j = 0; j < 4; j++)
#pragma unroll
                for (int e = 0; e < 4; e++) sacc[rt][j][e] = 0.0f;

        const u32 kB = sb + SMKV(cur);
#pragma unroll
        for (int kt = 0; kt < 4; kt++) {
#pragma unroll
            for (int jp = 0; jp < 2; jp++) {
                u32 k0r, k1r, k2r, k3r;
                ldsm4(swaddr(kB, jp * 16 + bRow, kt * 16 + bCol), k0r, k1r, k2r, k3r);
#pragma unroll
                for (int rt = 0; rt < 2; rt++) {
                    mma16816(sacc[rt][2 * jp],     qh[rt][kt][0], qh[rt][kt][1], qh[rt][kt][2], qh[rt][kt][3], k0r, k1r);
                    mma16816(sacc[rt][2 * jp + 1], qh[rt][kt][0], qh[rt][kt][1], qh[rt][kt][2], qh[rt][kt][3], k2r, k3r);
                }
            }
        }

        // ---- softmax: p' = 2^(s*log2e - 4); weight read from smem ----
        const u32 wB = sb + SMW(cur);
        u32 phf[2][4][2];
#pragma unroll
        for (int rt = 0; rt < 2; rt++) {
            const int rA = wrow0 + rt * 16;
            const int rB = rA + 8;
#pragma unroll
            for (int j = 0; j < 4; j++) {
                const int bA = qd * 2 + j * 8;
                const int chk = 2 * j + (qd >> 1);
                const int boff = (qd & 1) * 8;
                float2 wvA = *(const float2*)(smch + (wB - sb) + rA * 128 + ((chk ^ (rA & 7)) << 4) + boff);
                float2 wvB = *(const float2*)(smch + (wB - sb) + rB * 128 + ((chk ^ (rB & 7)) << 4) + boff);
                float s0 = ((mr[rt][0] >> bA) & 1u)       ? sacc[rt][j][0] + wvA.x : -30.0f;
                float s1 = ((mr[rt][0] >> (bA + 1)) & 1u) ? sacc[rt][j][1] + wvA.y : -30.0f;
                float s2 = ((mr[rt][1] >> bA) & 1u)       ? sacc[rt][j][2] + wvB.x : -30.0f;
                float s3 = ((mr[rt][1] >> (bA + 1)) & 1u) ? sacc[rt][j][3] + wvB.y : -30.0f;
                s0 = fminf(10.0f, fmaxf(-10.0f, s0));
                s1 = fminf(10.0f, fmaxf(-10.0f, s1));
                s2 = fminf(10.0f, fmaxf(-10.0f, s2));
                s3 = fminf(10.0f, fmaxf(-10.0f, s3));
                float p0 = ex2f(s0 * LOG2E - 4.0f);
                float p1 = ex2f(s1 * LOG2E - 4.0f);
                float p2 = ex2f(s2 * LOG2E - 4.0f);
                float p3 = ex2f(s3 * LOG2E - 4.0f);
                lsum[rt][0] += p0 + p1;
                lsum[rt][1] += p2 + p3;
                phf[rt][j][0] = packhf(p0, p1);
                phf[rt][j][1] = packhf(p2, p3);
            }
        }

        // ---- O += P' @ V : shared V frags across both row-tiles ----
        const u32 vB = sb + SMKV(cur) + 4096;
#pragma unroll
        for (int kt = 0; kt < 2; kt++) {
#pragma unroll
            for (int jp = 0; jp < 4; jp++) {
                u32 v0r, v1r, v2r, v3r;
                ldsm4(swaddr(vB, jp * 16 + bRow, kt * 16 + bCol), v0r, v1r, v2r, v3r);
#pragma unroll
                for (int rt = 0; rt < 2; rt++) {
                    u32 a0 = phf[rt][2 * kt][0], a1 = phf[rt][2 * kt][1];
                    u32 a2 = phf[rt][2 * kt + 1][0], a3 = phf[rt][2 * kt + 1][1];
                    mma16816(oacc[rt][2 * jp],     a0, a1, a2, a3, v0r, v1r);
                    mma16816(oacc[rt][2 * jp + 1], a0, a1, a2, a3, v2r, v3r);
                }
            }
        }

        if (i + 1 < niter) cp_wait0();
        __syncthreads();
    }

    // ---- epilogue: partial O + partial l (additive across splits) ----
    const size_t po = ((size_t)(split * H + head) * NA);
#pragma unroll
    for (int rt = 0; rt < 2; rt++) {
        float lA = lsum[rt][0], lB = lsum[rt][1];
        lA += __shfl_xor_sync(0xffffffffu, lA, 1);
        lA += __shfl_xor_sync(0xffffffffu, lA, 2);
        lB += __shfl_xor_sync(0xffffffffu, lB, 1);
        lB += __shfl_xor_sync(0xffffffffu, lB, 2);
        const int rGA = rbase + rt * 16;
        const int rGB = rGA + 8;
        if (qd == 0) {
            g_pl[po + rGA] = lA;
            g_pl[po + rGB] = lB;
        }
        float* pA = g_pO + (po + rGA) * DK + qd * 2;
        float* pB = g_pO + (po + rGB) * DK + qd * 2;
#pragma unroll
        for (int j = 0; j < 8; j++) {
            *(float2*)(pA + j * 8) = make_float2(oacc[rt][j][0], oacc[rt][j][1]);
            *(float2*)(pB + j * 8) = make_float2(oacc[rt][j][2], oacc[rt][j][3]);
        }
    }
}

// ---------------- finalize: combine splits, head mean, influence ----------------
__global__ __launch_bounds__(256) void finalize_kernel(float* __restrict__ out)
{
    int idx = blockIdx.x * blockDim.x + threadIdx.x;   // 0..65535
    if (idx < NA * DK / 4) {
        const int row = idx >> 4;
        const int c4 = (idx & 15) * 4;
        float ax = 0.f, ay = 0.f, az = 0.f, aw = 0.f;
#pragma unroll
        for (int h = 0; h < H; h++) {
            float ox = 0.f, oy = 0.f, oz = 0.f, ow = 0.f, l = 0.f;
#pragma unroll
            for (int s = 0; s < KSPLIT; s++) {
                const float4 v = *(const float4*)&g_pO[((size_t)(s * H + h) * NA + row) * DK + c4];
                ox += v.x; oy += v.y; oz += v.z; ow += v.w;
                l += g_pl[(size_t)(s * H + h) * NA + row];
            }
            const float inv = 1.0f / l;
            ax += ox * inv; ay += oy * inv; az += oz * inv; aw += ow * inv;
        }
        *(float4*)&out[(size_t)row * DK + c4] =
            make_float4(ax * 0.25f, ay * 0.25f, az * 0.25f, aw * 0.25f);
    }
    if (idx < NA) {
        out[NA * DK + idx] = 1.0f;   // softmax rows sum to exactly 1
    }
}

// ---------------- launch ----------------
extern "C" void kernel_launch(void* const* d_in, const int* in_sizes, int n_in,
                              void* d_out, int out_size)
{
    const float* a_z    = (const float*)d_in[0];
    const float* bv_z   = (const float*)d_in[1];
    const void*  maskp  = d_in[2];
    const float* weight = (const float*)d_in[3];
    const float* Wq     = (const float*)d_in[4];
    const float* Wk     = (const float*)d_in[5];
    const float* Wv     = (const float*)d_in[6];
    float* out = (float*)d_out;

    cudaFuncSetAttribute(attn_kernel, cudaFuncAttributeMaxDynamicSharedMemorySize, SM_TOTAL);

    projtc_kernel<<<dim3(32, 8, 4), 128>>>(a_z, bv_z, Wq, Wk, Wv,
        (const unsigned char*)maskp, (const int*)maskp);
    attn_kernel<<<dim3(H, NA / BM, KSPLIT), 128, SM_TOTAL>>>(weight);
    finalize_kernel<<<(NA * DK / 4 + 255) / 256, 256>>>(out);
}